// round 1
// baseline (speedup 1.0000x reference)
#include <cuda_runtime.h>
#include <math.h>

#define CCH 512    // channels
#define ND  512    // dict rows
#define HWV 4096   // H*W
#define MT  128    // pixels per block
#define KT  16     // k chunk

typedef unsigned long long u64;

__device__ float g_dnormT[CCH * ND];  // normalized dict, transposed: [k][n]

// ---------------- prep: normalize dict rows, store transposed ----------------
__global__ void prep_kernel(const float* __restrict__ dict) {
    int n = blockIdx.x;
    const float* row = dict + n * CCH;
    float s = 0.f;
    for (int k = threadIdx.x; k < CCH; k += 128) {
        float v = row[k];
        s = fmaf(v, v, s);
    }
#pragma unroll
    for (int o = 16; o; o >>= 1) s += __shfl_xor_sync(0xffffffffu, s, o);
    __shared__ float red[4];
    if ((threadIdx.x & 31) == 0) red[threadIdx.x >> 5] = s;
    __syncthreads();
    float norm = sqrtf(red[0] + red[1] + red[2] + red[3]);
    for (int k = threadIdx.x; k < CCH; k += 128) {
        g_dnormT[k * ND + n] = row[k] / norm;
    }
}

// ---------------- shared memory plan (union, phases separated by syncs) ------
struct SmemGemm {
    float AsD[KT][2 * MT];   // x tile, each pixel value duplicated (for f32x2) 16KB
    float Bs[KT][MT];        // d_normT tile                                    8KB
};
struct SmemRed {
    float bv[MT][16];
    int   bi[MT][16];
};
struct SmemRows {
    float rows[MT][65];      // staged dict rows (65: conflict-free transposed read)
};
union __align__(16) SmemU {
    SmemGemm g;
    float sumsq[8][MT];
    SmemRed r;
    SmemRows rw;
};

// ---------------- main fused kernel ----------------
__global__ void __launch_bounds__(256, 2)
negdict_kernel(const float* __restrict__ x, const float* __restrict__ dict,
               float* __restrict__ out) {
    __shared__ SmemU sm;
    __shared__ float s_negq[MT];   // -0.25 * ||x_pixel||
    __shared__ int   s_idx[MT];
    __shared__ int   s_rep[MT];

    const int tid = threadIdx.x;
    const int tx = tid & 15;       // n-dim thread coord (16)
    const int ty = tid >> 4;       // px-dim thread coord (16)
    const int mt = blockIdx.x;     // 512 tiles
    const int b = mt >> 5;         // 32 tiles per image
    const int hw0 = (mt & 31) * MT;
    const float* xb = x + (size_t)b * CCH * HWV + hw0;

    const int lp4 = (tid & 31) * 4;  // load: pixel offset (float4)
    const int lk  = tid >> 5;        // load: k row 0..7

    float bestv[8];
    int   besti[8];
#pragma unroll
    for (int i = 0; i < 8; i++) { bestv[i] = -1e30f; besti[i] = 0; }

    float ssq0 = 0.f, ssq1 = 0.f, ssq2 = 0.f, ssq3 = 0.f;

    for (int nt = 0; nt < 4; nt++) {
        const int n0 = nt * 128;
        u64 acc[8][4];
#pragma unroll
        for (int i = 0; i < 8; i++)
#pragma unroll
            for (int j = 0; j < 4; j++) acc[i][j] = 0ull;

        for (int kc = 0; kc < CCH; kc += KT) {
#pragma unroll
            for (int pass = 0; pass < 2; pass++) {
                int k = lk + pass * 8;
                float4 v = *(const float4*)(xb + (size_t)(kc + k) * HWV + lp4);
                if (nt == 0) {
                    ssq0 = fmaf(v.x, v.x, ssq0);
                    ssq1 = fmaf(v.y, v.y, ssq1);
                    ssq2 = fmaf(v.z, v.z, ssq2);
                    ssq3 = fmaf(v.w, v.w, ssq3);
                }
                // duplicated store: (x,x,y,y) (z,z,w,w) so LDS gives packed f32x2 pairs
                *(float4*)&sm.g.AsD[k][lp4 * 2]     = make_float4(v.x, v.x, v.y, v.y);
                *(float4*)&sm.g.AsD[k][lp4 * 2 + 4] = make_float4(v.z, v.z, v.w, v.w);
                float4 w = *(const float4*)(g_dnormT + (size_t)(kc + k) * ND + n0 + lp4);
                *(float4*)&sm.g.Bs[k][lp4] = w;
            }
            __syncthreads();
#pragma unroll
            for (int k = 0; k < KT; k++) {
                u64 a2[8], b2[4];
                ulonglong2 t;
                t = *(const ulonglong2*)&sm.g.AsD[k][ty * 8];           a2[0] = t.x; a2[1] = t.y;
                t = *(const ulonglong2*)&sm.g.AsD[k][ty * 8 + 4];       a2[2] = t.x; a2[3] = t.y;
                t = *(const ulonglong2*)&sm.g.AsD[k][128 + ty * 8];     a2[4] = t.x; a2[5] = t.y;
                t = *(const ulonglong2*)&sm.g.AsD[k][128 + ty * 8 + 4]; a2[6] = t.x; a2[7] = t.y;
                t = *(const ulonglong2*)&sm.g.Bs[k][tx * 4];            b2[0] = t.x; b2[1] = t.y;
                t = *(const ulonglong2*)&sm.g.Bs[k][64 + tx * 4];       b2[2] = t.x; b2[3] = t.y;
#pragma unroll
                for (int i = 0; i < 8; i++)
#pragma unroll
                    for (int j = 0; j < 4; j++)
                        asm("fma.rn.f32x2 %0, %1, %2, %0;"
                            : "+l"(acc[i][j]) : "l"(a2[i]), "l"(b2[j]));
            }
            __syncthreads();
        }

        if (nt == 0) {
            // stash per-thread sumsq partials (reuses AsD region; loop just synced)
            sm.sumsq[lk][lp4 + 0] = ssq0;
            sm.sumsq[lk][lp4 + 1] = ssq1;
            sm.sumsq[lk][lp4 + 2] = ssq2;
            sm.sumsq[lk][lp4 + 3] = ssq3;
            __syncthreads();
            if (tid < MT) {
                float s = 0.f;
#pragma unroll
                for (int r = 0; r < 8; r++) s += sm.sumsq[r][tid];
                s_negq[tid] = -0.25f * sqrtf(s);
            }
            __syncthreads();
        }

        // fold this n-tile into running argmax (ascending n order; strict > keeps first)
#pragma unroll
        for (int i = 0; i < 8; i++) {
#pragma unroll
            for (int j = 0; j < 4; j++) {
                float lo = __uint_as_float((unsigned)(acc[i][j] & 0xffffffffull));
                float hi = __uint_as_float((unsigned)(acc[i][j] >> 32));
                int nb = n0 + ((j < 2) ? (tx * 4 + 2 * j) : (64 + tx * 4 + 2 * (j - 2)));
                if (lo > bestv[i]) { bestv[i] = lo; besti[i] = nb; }
                if (hi > bestv[i]) { bestv[i] = hi; besti[i] = nb + 1; }
            }
        }
    }

    __syncthreads();
#pragma unroll
    for (int i = 0; i < 8; i++) {
        int p = (i < 4) ? (ty * 4 + i) : (64 + ty * 4 + i - 4);
        sm.r.bv[p][tx] = bestv[i];
        sm.r.bi[p][tx] = besti[i];
    }
    __syncthreads();
    if (tid < MT) {
        float bv = -1e30f; int bi = 0x7fffffff;
#pragma unroll
        for (int t = 0; t < 16; t++) {
            float v = sm.r.bv[tid][t];
            int   ii = sm.r.bi[tid][t];
            if (v > bv || (v == bv && ii < bi)) { bv = v; bi = ii; }
        }
        s_idx[tid] = bi;
        // replace <=> apm < 0.625 <=> max_sim > -0.25 <=> max_dot > -0.25*||x||
        s_rep[tid] = (bv > s_negq[tid]) ? 1 : 0;
    }
    __syncthreads();

    // ---------------- epilogue: staged gather + coalesced strided writes ----
    float* outb = out + (size_t)b * CCH * HWV + hw0;
    for (int c0 = 0; c0 < CCH; c0 += 64) {
#pragma unroll
        for (int it = 0; it < 8; it++) {
            int lin = it * 256 + tid;       // 0..2047 over [p:128][cq:16]
            int p = lin >> 4;
            int cq = (lin & 15) * 4;
            float4 v = *(const float4*)(dict + (size_t)s_idx[p] * CCH + c0 + cq);
            sm.rw.rows[p][cq + 0] = v.x;
            sm.rw.rows[p][cq + 1] = v.y;
            sm.rw.rows[p][cq + 2] = v.z;
            sm.rw.rows[p][cq + 3] = v.w;
        }
        __syncthreads();
#pragma unroll
        for (int it = 0; it < 32; it++) {
            int lin = it * 256 + tid;       // 0..8191 over [c:64][p:128]
            int c = c0 + (lin >> 7);
            int p = lin & 127;
            float v = sm.rw.rows[p][c - c0];
            if (!s_rep[p]) v = xb[(size_t)c * HWV + p];
            outb[(size_t)c * HWV + p] = v;
        }
        __syncthreads();
    }
}

// ---------------- launch ----------------
extern "C" void kernel_launch(void* const* d_in, const int* in_sizes, int n_in,
                              void* d_out, int out_size) {
    const float* x;
    const float* nd;
    if (n_in >= 2 && in_sizes[0] == ND * CCH && in_sizes[1] != ND * CCH) {
        nd = (const float*)d_in[0];
        x  = (const float*)d_in[1];
    } else {
        x  = (const float*)d_in[0];
        nd = (const float*)d_in[1];
    }
    float* out = (float*)d_out;

    prep_kernel<<<ND, 128>>>(nd);
    negdict_kernel<<<512, 256>>>(x, nd, out);
}

// round 2
// speedup vs baseline: 1.3490x; 1.3490x over previous
#include <cuda_runtime.h>
#include <math.h>

#define CCH 512    // channels (K)
#define ND  512    // dict rows (N total)
#define HWV 4096   // H*W
#define MT  128    // pixels per block tile
#define KT  16     // k chunk
#define NCH (CCH / KT)   // 32 chunks per n-tile
#define BUFS 4

typedef unsigned long long u64;

__device__ float g_dnormT[CCH * ND];  // normalized dict, transposed: [k][n]

// ---------------- prep: normalize dict rows, store transposed ----------------
__global__ void prep_kernel(const float* __restrict__ dict) {
    int n = blockIdx.x;
    const float* row = dict + n * CCH;
    float s = 0.f;
    for (int k = threadIdx.x; k < CCH; k += 128) {
        float v = row[k];
        s = fmaf(v, v, s);
    }
#pragma unroll
    for (int o = 16; o; o >>= 1) s += __shfl_xor_sync(0xffffffffu, s, o);
    __shared__ float red[4];
    if ((threadIdx.x & 31) == 0) red[threadIdx.x >> 5] = s;
    __syncthreads();
    float norm = sqrtf(red[0] + red[1] + red[2] + red[3]);
    for (int k = threadIdx.x; k < CCH; k += 128) {
        g_dnormT[k * ND + n] = row[k] / norm;
    }
}

// ---------------- shared memory (union; phases separated by barriers) --------
union __align__(16) SmemU {
    float sbuf[BUFS][2 * KT * MT];  // per buf: A tile [KT][128] then B tile [KT][128]
    struct { float bv[MT][16]; int bi[MT][16]; } r;
    struct { float rows[MT][65]; } rw;
};

#define CP16(dst, src) \
    asm volatile("cp.async.cg.shared.global [%0], [%1], 16;" :: "r"(dst), "l"(src) : "memory")
#define CP_COMMIT() asm volatile("cp.async.commit_group;" ::: "memory")
#define CP_WAIT2()  asm volatile("cp.async.wait_group 2;" ::: "memory")

// one 16-k chunk of FMAs: acc[i][j] = (dot px-pair i) for n slot j
template <int SSQ>
__device__ __forceinline__ void compute_chunk(
    const float* __restrict__ A, const float* __restrict__ B,
    int tx, int ty, u64 (&acc)[4][8], u64 (&ssq2)[4])
{
#pragma unroll
    for (int k = 0; k < KT; k++) {
        u64 a2[4];
        ulonglong2 t;
        t = *(const ulonglong2*)&A[k * MT + ty * 4];        a2[0] = t.x; a2[1] = t.y;
        t = *(const ulonglong2*)&A[k * MT + 64 + ty * 4];   a2[2] = t.x; a2[3] = t.y;
        float4 b0 = *(const float4*)&B[k * MT + tx * 4];
        float4 b1 = *(const float4*)&B[k * MT + 64 + tx * 4];
        float bf[8] = {b0.x, b0.y, b0.z, b0.w, b1.x, b1.y, b1.z, b1.w};
        if (SSQ) {
#pragma unroll
            for (int i = 0; i < 4; i++)
                asm("fma.rn.f32x2 %0, %1, %1, %0;" : "+l"(ssq2[i]) : "l"(a2[i]));
        }
#pragma unroll
        for (int j = 0; j < 8; j++) {
            u64 bb;
            asm("mov.b64 %0, {%1, %1};" : "=l"(bb) : "f"(bf[j]));
#pragma unroll
            for (int i = 0; i < 4; i++)
                asm("fma.rn.f32x2 %0, %1, %2, %0;" : "+l"(acc[i][j]) : "l"(a2[i]), "l"(bb));
        }
    }
}

// ---------------- main fused kernel ----------------
__global__ void __launch_bounds__(256, 2)
negdict_kernel(const float* __restrict__ x, const float* __restrict__ dict,
               float* __restrict__ out) {
    __shared__ SmemU sm;
    __shared__ float s_negq[MT];   // -0.25 * ||x_pixel||
    __shared__ int   s_idx[MT];
    __shared__ int   s_rep[MT];

    const int tid = threadIdx.x;
    const int tx = tid & 15;       // n-dim thread coord
    const int ty = tid >> 4;       // px-dim thread coord
    const int mt = blockIdx.x;     // 512 tiles
    const int b = mt >> 5;
    const int hw0 = (mt & 31) * MT;
    const float* xb = x + (size_t)b * CCH * HWV + hw0;

    float bestv[8];
    int   besti[8];
#pragma unroll
    for (int s = 0; s < 8; s++) { bestv[s] = -1e30f; besti[s] = 0; }

    u64 ssq2[4] = {0ull, 0ull, 0ull, 0ull};

    // cp.async issue of chunk c (rows kc..kc+KT-1) into ring buffer
    auto issue = [&](int c, int n0) {
        int buf = c & (BUFS - 1);
        int kc = c * KT;
#pragma unroll
        for (int t = 0; t < 2; t++) {
            int idx = tid + t * 256;        // 0..511 over [row:16][q:32]
            int r = idx >> 5;
            int q = idx & 31;
            unsigned da = (unsigned)__cvta_generic_to_shared(&sm.sbuf[buf][r * MT + q * 4]);
            CP16(da, xb + (size_t)(kc + r) * HWV + q * 4);
            unsigned db = (unsigned)__cvta_generic_to_shared(&sm.sbuf[buf][KT * MT + r * MT + q * 4]);
            CP16(db, g_dnormT + (size_t)(kc + r) * ND + n0 + q * 4);
        }
    };

    for (int nt = 0; nt < 4; nt++) {
        const int n0 = nt * 128;
        u64 acc[4][8];
#pragma unroll
        for (int i = 0; i < 4; i++)
#pragma unroll
            for (int j = 0; j < 8; j++) acc[i][j] = 0ull;

        issue(0, n0); CP_COMMIT();
        issue(1, n0); CP_COMMIT();

        for (int c = 0; c < NCH; c++) {
            if (c + 2 < NCH) issue(c + 2, n0);
            CP_COMMIT();
            CP_WAIT2();
            __syncthreads();
            const float* A = &sm.sbuf[c & (BUFS - 1)][0];
            const float* B = &sm.sbuf[c & (BUFS - 1)][KT * MT];
            if (nt == 0) compute_chunk<1>(A, B, tx, ty, acc, ssq2);
            else         compute_chunk<0>(A, B, tx, ty, acc, ssq2);
        }

        if (nt == 0 && tx == 0) {
            // pixels for pair i, half h: p = (i<2 ? ty*4+2i+h : 64+ty*4+2(i-2)+h)
#pragma unroll
            for (int i = 0; i < 4; i++) {
                float lo = __uint_as_float((unsigned)(ssq2[i] & 0xffffffffull));
                float hi = __uint_as_float((unsigned)(ssq2[i] >> 32));
                int p0 = (i < 2) ? (ty * 4 + 2 * i) : (64 + ty * 4 + 2 * (i - 2));
                s_negq[p0]     = -0.25f * sqrtf(lo);
                s_negq[p0 + 1] = -0.25f * sqrtf(hi);
            }
        }

        // fold this n-tile into running argmax (n ascending; strict > keeps lowest n)
#pragma unroll
        for (int j = 0; j < 8; j++) {
            int nb = n0 + ((j < 4) ? (tx * 4 + j) : (64 + tx * 4 + (j - 4)));
#pragma unroll
            for (int i = 0; i < 4; i++) {
                float lo = __uint_as_float((unsigned)(acc[i][j] & 0xffffffffull));
                float hi = __uint_as_float((unsigned)(acc[i][j] >> 32));
                int s = 2 * i;
                if (lo > bestv[s])     { bestv[s]     = lo; besti[s]     = nb; }
                if (hi > bestv[s + 1]) { bestv[s + 1] = hi; besti[s + 1] = nb; }
            }
        }
    }

    __syncthreads();   // all compute done before smem union reuse
#pragma unroll
    for (int s = 0; s < 8; s++) {
        int i = s >> 1, h = s & 1;
        int p = (i < 2) ? (ty * 4 + 2 * i + h) : (64 + ty * 4 + 2 * (i - 2) + h);
        sm.r.bv[p][tx] = bestv[s];
        sm.r.bi[p][tx] = besti[s];
    }
    __syncthreads();
    if (tid < MT) {
        float bv = -1e30f; int bi = 0x7fffffff;
#pragma unroll
        for (int t = 0; t < 16; t++) {
            float v = sm.r.bv[tid][t];
            int   ii = sm.r.bi[tid][t];
            if (v > bv || (v == bv && ii < bi)) { bv = v; bi = ii; }
        }
        s_idx[tid] = bi;
        // replace <=> apm < 0.625 <=> max_sim > -0.25 <=> max_dot > -0.25*||x||
        s_rep[tid] = (bv > s_negq[tid]) ? 1 : 0;
    }
    __syncthreads();

    // ---------------- epilogue: staged gather + coalesced strided writes ----
    float* outb = out + (size_t)b * CCH * HWV + hw0;
    for (int c0 = 0; c0 < CCH; c0 += 64) {
#pragma unroll
        for (int it = 0; it < 8; it++) {
            int lin = it * 256 + tid;       // over [p:128][cq:16]
            int p = lin >> 4;
            int cq = (lin & 15) * 4;
            float4 v = *(const float4*)(dict + (size_t)s_idx[p] * CCH + c0 + cq);
            sm.rw.rows[p][cq + 0] = v.x;
            sm.rw.rows[p][cq + 1] = v.y;
            sm.rw.rows[p][cq + 2] = v.z;
            sm.rw.rows[p][cq + 3] = v.w;
        }
        __syncthreads();
#pragma unroll
        for (int it = 0; it < 32; it++) {
            int lin = it * 256 + tid;       // over [c:64][p:128]
            int c = c0 + (lin >> 7);
            int p = lin & 127;
            float v = sm.rw.rows[p][c - c0];
            if (!s_rep[p]) v = xb[(size_t)c * HWV + p];
            outb[(size_t)c * HWV + p] = v;
        }
        __syncthreads();
    }
}

// ---------------- launch ----------------
extern "C" void kernel_launch(void* const* d_in, const int* in_sizes, int n_in,
                              void* d_out, int out_size) {
    const float* x;
    const float* nd;
    if (n_in >= 2 && in_sizes[0] == ND * CCH && in_sizes[1] != ND * CCH) {
        nd = (const float*)d_in[0];
        x  = (const float*)d_in[1];
    } else {
        x  = (const float*)d_in[0];
        nd = (const float*)d_in[1];
    }
    float* out = (float*)d_out;

    prep_kernel<<<ND, 128>>>(nd);
    negdict_kernel<<<512, 256>>>(x, nd, out);
}

// round 4
// speedup vs baseline: 1.9005x; 1.4089x over previous
#include <cuda_runtime.h>
#include <cuda_fp16.h>
#include <math.h>
#include <stdint.h>

#define CCH 512
#define ND  512
#define HWV 4096
#define NPX 65536
#define MT  128
#define KCH 32
#define TOTCH 64          // 4 n-tiles * 16 k-chunks
#define MARGIN 1e-5f

#define SW64(o) ((o) ^ (((o) >> 3) & 0x30))

typedef unsigned int u32;

// ---------------- device scratch ----------------
__device__ float g_negq[NPX];
__device__ __align__(16) __half g_Ahi[(size_t)NPX * CCH];
__device__ __align__(16) __half g_Alo[(size_t)NPX * CCH];
__device__ __align__(16) __half g_Bhi[ND * CCH];
__device__ __align__(16) __half g_Blo[ND * CCH];
__device__ float g_dnorm[ND * CCH];

// ---------------- PTX helpers ----------------
__device__ __forceinline__ u32 smem_u32(const void* p) {
    u32 a;
    asm("{ .reg .u64 t; cvta.to.shared.u64 t, %1; cvt.u32.u64 %0, t; }" : "=r"(a) : "l"(p));
    return a;
}
#define CP16(dst, src) \
    asm volatile("cp.async.cg.shared.global [%0], [%1], 16;" :: "r"(dst), "l"(src) : "memory")
#define CP_COMMIT() asm volatile("cp.async.commit_group;" ::: "memory")
#define CP_WAIT2()  asm volatile("cp.async.wait_group 2;" ::: "memory")

#define LDSM4(r, addr) \
    asm volatile("ldmatrix.sync.aligned.m8n8.x4.shared.b16 {%0,%1,%2,%3}, [%4];" \
        : "=r"((r)[0]), "=r"((r)[1]), "=r"((r)[2]), "=r"((r)[3]) : "r"(addr))

#define MMA16816(d, a, b0, b1) \
    asm volatile("mma.sync.aligned.m16n8k16.row.col.f32.f16.f16.f32 " \
        "{%0,%1,%2,%3},{%4,%5,%6,%7},{%8,%9},{%0,%1,%2,%3};" \
        : "+f"((d)[0]), "+f"((d)[1]), "+f"((d)[2]), "+f"((d)[3]) \
        : "r"((a)[0]), "r"((a)[1]), "r"((a)[2]), "r"((a)[3]), "r"(b0), "r"(b1))

// ---------------- prep: dict -> dnorm fp32 + fp16 hi/lo [n][k] --------------
__global__ void prep_dict(const float* __restrict__ dict) {
    int n = blockIdx.x;
    const float* row = dict + n * CCH;
    float s = 0.f;
    for (int k = threadIdx.x; k < CCH; k += 128) {
        float v = row[k];
        s = fmaf(v, v, s);
    }
#pragma unroll
    for (int o = 16; o; o >>= 1) s += __shfl_xor_sync(0xffffffffu, s, o);
    __shared__ float red[4];
    if ((threadIdx.x & 31) == 0) red[threadIdx.x >> 5] = s;
    __syncthreads();
    float norm = sqrtf(red[0] + red[1] + red[2] + red[3]);
    for (int k = threadIdx.x; k < CCH; k += 128) {
        float v = row[k] / norm;
        g_dnorm[n * CCH + k] = v;
        __half h = __float2half(v);
        g_Bhi[n * CCH + k] = h;
        g_Blo[n * CCH + k] = __float2half(v - __half2float(h));
    }
}

// ---------------- prep: x -> transposed fp16 hi/lo [px][k] + negq -----------
__global__ void __launch_bounds__(256, 1)
prep_x(const float* __restrict__ x) {
    __shared__ float tile[64][132];
    const int tid = threadIdx.x;
    const int p0 = blockIdx.x * 128;
    const int b = p0 >> 12;
    const int hw0 = p0 & 4095;
    const float* xb = x + (size_t)b * CCH * HWV + hw0;
    float acc[4] = {0.f, 0.f, 0.f, 0.f};

    for (int c = 0; c < 8; c++) {           // 8 chunks of 64 k
        __syncthreads();
#pragma unroll
        for (int i = 0; i < 8; i++) {
            int lin = i * 256 + tid;
            int r = lin >> 5;
            int j = lin & 31;
            float4 v = *(const float4*)(xb + (size_t)(c * 64 + r) * HWV + j * 4);
            tile[r][j * 4 + 0] = v.x;
            tile[r][j * 4 + 1] = v.y;
            tile[r][j * 4 + 2] = v.z;
            tile[r][j * 4 + 3] = v.w;
        }
        __syncthreads();
#pragma unroll
        for (int i = 0; i < 4; i++) {
            int lin = i * 256 + tid;
            int p = lin >> 3;               // 0..127
            int g = lin & 7;                // 8 k-groups of 8
            union { __half h[8]; uint4 v; } hi8, lo8;
            float s = 0.f;
#pragma unroll
            for (int u = 0; u < 8; u++) {
                float v = tile[g * 8 + u][p];
                s = fmaf(v, v, s);
                __half h = __float2half(v);
                hi8.h[u] = h;
                lo8.h[u] = __float2half(v - __half2float(h));
            }
            s += __shfl_xor_sync(0xffffffffu, s, 1);
            s += __shfl_xor_sync(0xffffffffu, s, 2);
            s += __shfl_xor_sync(0xffffffffu, s, 4);
            acc[i] += s;
            size_t off = (size_t)(p0 + p) * CCH + c * 64 + g * 8;
            *(uint4*)(g_Ahi + off) = hi8.v;
            *(uint4*)(g_Alo + off) = lo8.v;
        }
    }
#pragma unroll
    for (int i = 0; i < 4; i++) {
        int lin = i * 256 + tid;
        int p = lin >> 3;
        int g = lin & 7;
        if (g == 0) g_negq[p0 + p] = -0.25f * sqrtf(acc[i]);
    }
}

// ---------------- main: split-fp16 mma.sync GEMM + top2/rescore + blend -----
__global__ void __launch_bounds__(256, 1)
negdict_mma(const float* __restrict__ x, const float* __restrict__ dict,
            float* __restrict__ out) {
    extern __shared__ __align__(16) char dsm[];   // 4 bufs * 32KB
    __shared__ union {
        struct { float bv1[MT][8]; float bv2[MT][8]; int bi1[MT][8]; int bi2[MT][8]; } red;
        float rows[MT][65];
    } su;
    __shared__ int s_idx[MT];
    __shared__ int s_rep[MT];

    const int tid = threadIdx.x;
    const int wid = tid >> 5;
    const int lid = tid & 31;
    const int wm = wid >> 1;          // 0..3  (32 px each)
    const int wn = wid & 1;           // 0..1  (64 n each)
    const int pxbase = blockIdx.x * MT;
    const int b = pxbase >> 12;
    const int hw0 = pxbase & 4095;

    const u32 sbase = smem_u32(dsm);

    // per-lane swizzled ldmatrix offsets (relative within a tile)
    u32 offA[2], offB[4];
#pragma unroll
    for (int t = 0; t < 2; t++) {
        int rowA = wm * 32 + t * 16 + (lid & 7) + 8 * ((lid >> 3) & 1);
        int kA = (lid >> 4) << 4;
        offA[t] = SW64((u32)(rowA * 64 + kA));
    }
#pragma unroll
    for (int g = 0; g < 4; g++) {
        int rowB = wn * 64 + g * 16 + (lid & 7) + 8 * (lid >> 4);
        int kB = ((lid >> 3) & 1) << 4;
        offB[g] = SW64((u32)(rowB * 64 + kB));
    }

    float acc[2][8][4];
#pragma unroll
    for (int t = 0; t < 2; t++)
#pragma unroll
        for (int j = 0; j < 8; j++)
#pragma unroll
            for (int q = 0; q < 4; q++) acc[t][j][q] = 0.f;

    float bv1s[4], bv2s[4];
    int bi1s[4], bi2s[4];
#pragma unroll
    for (int s = 0; s < 4; s++) {
        bv1s[s] = -1e30f; bv2s[s] = -1e30f;
        bi1s[s] = 0x7fffffff; bi2s[s] = 0x7fffffff;
    }

    auto issue = [&](int cc) {
        u32 bufb = sbase + (cc & 3) * 32768;
        int nt = cc >> 4;
        int kc = (cc & 15) * KCH;
#pragma unroll
        for (int it = 0; it < 2; it++) {
            int u = tid + it * 256;          // 0..511
            int row = u >> 2;
            int g = u & 3;
            u32 dsw = SW64((u32)(row * 64 + g * 16));
            size_t aoff = (size_t)(pxbase + row) * CCH + kc + g * 8;
            CP16(bufb + dsw,         g_Ahi + aoff);
            CP16(bufb + 8192 + dsw,  g_Alo + aoff);
            size_t boff = (size_t)(nt * 128 + row) * CCH + kc + g * 8;
            CP16(bufb + 16384 + dsw, g_Bhi + boff);
            CP16(bufb + 24576 + dsw, g_Blo + boff);
        }
        CP_COMMIT();
    };

    issue(0); issue(1); issue(2);

    for (int cc = 0; cc < TOTCH; cc++) {
        CP_WAIT2();
        __syncthreads();
        if (cc + 3 < TOTCH) issue(cc + 3);
        else CP_COMMIT();

        u32 bufb = sbase + (cc & 3) * 32768;
#pragma unroll
        for (int s = 0; s < 2; s++) {
            u32 kx = (u32)(s << 5);
            u32 Ah[2][4], Al[2][4], Bh[4][4], Bl[4][4];
#pragma unroll
            for (int t = 0; t < 2; t++) {
                LDSM4(Ah[t], bufb + (offA[t] ^ kx));
                LDSM4(Al[t], bufb + 8192 + (offA[t] ^ kx));
            }
#pragma unroll
            for (int g = 0; g < 4; g++) {
                LDSM4(Bh[g], bufb + 16384 + (offB[g] ^ kx));
                LDSM4(Bl[g], bufb + 24576 + (offB[g] ^ kx));
            }
#pragma unroll
            for (int t = 0; t < 2; t++)
#pragma unroll
                for (int j = 0; j < 8; j++)
                    MMA16816(acc[t][j], Ah[t], Bh[j >> 1][(j & 1) * 2], Bh[j >> 1][(j & 1) * 2 + 1]);
#pragma unroll
            for (int t = 0; t < 2; t++)
#pragma unroll
                for (int j = 0; j < 8; j++)
                    MMA16816(acc[t][j], Ah[t], Bl[j >> 1][(j & 1) * 2], Bl[j >> 1][(j & 1) * 2 + 1]);
#pragma unroll
            for (int t = 0; t < 2; t++)
#pragma unroll
                for (int j = 0; j < 8; j++)
                    MMA16816(acc[t][j], Al[t], Bh[j >> 1][(j & 1) * 2], Bh[j >> 1][(j & 1) * 2 + 1]);
        }

        if ((cc & 15) == 15) {
            // fold n-tile into per-lane top-2, ascending n
            int nt = cc >> 4;
            int nbase = nt * 128 + wn * 64;
#pragma unroll
            for (int j = 0; j < 8; j++) {
                int nb = nbase + (j >> 1) * 16 + (j & 1) * 8 + 2 * (lid & 3);
#pragma unroll
                for (int t = 0; t < 2; t++) {
#pragma unroll
                    for (int q = 0; q < 4; q++) {
                        int s = 2 * t + (q >> 1);       // slot: row-half
                        int n = nb + (q & 1);
                        float v = acc[t][j][q];
                        if (v > bv1s[s]) {
                            bv2s[s] = bv1s[s]; bi2s[s] = bi1s[s];
                            bv1s[s] = v;       bi1s[s] = n;
                        } else if (v > bv2s[s]) {
                            bv2s[s] = v; bi2s[s] = n;
                        }
                        acc[t][j][q] = 0.f;
                    }
                }
            }
        }
    }

    // ---------------- cross-lane reduction -----------------------------------
    __syncthreads();
#pragma unroll
    for (int t = 0; t < 2; t++)
#pragma unroll
        for (int h = 0; h < 2; h++) {
            int s = 2 * t + h;
            int p = wm * 32 + t * 16 + (lid >> 2) + 8 * h;
            int col = wn * 4 + (lid & 3);
            su.red.bv1[p][col] = bv1s[s];
            su.red.bv2[p][col] = bv2s[s];
            su.red.bi1[p][col] = bi1s[s];
            su.red.bi2[p][col] = bi2s[s];
        }
    __syncthreads();

    if (tid < MT) {
        float B1 = -1e30f, B2 = -1e30f;
        int I1 = 0x7fffffff, I2 = 0x7fffffff;
#pragma unroll
        for (int col = 0; col < 8; col++) {
#pragma unroll
            for (int w = 0; w < 2; w++) {
                float v = w ? su.red.bv2[tid][col] : su.red.bv1[tid][col];
                int   i = w ? su.red.bi2[tid][col] : su.red.bi1[tid][col];
                if (v > B1 || (v == B1 && i < I1)) {
                    B2 = B1; I2 = I1; B1 = v; I1 = i;
                } else if (v > B2 || (v == B2 && i < I2)) {
                    B2 = v; I2 = i;
                }
            }
        }
        int bi = I1;
        if (B1 - B2 < MARGIN) {
            // exact fp32 rescore of the two candidates
            const float* xp = x + (size_t)b * CCH * HWV + hw0 + tid;
            const float* d1 = g_dnorm + (size_t)I1 * CCH;
            const float* d2 = g_dnorm + (size_t)I2 * CCH;
            float s1 = 0.f, s2 = 0.f;
            for (int k = 0; k < CCH; k++) {
                float xv = xp[(size_t)k * HWV];
                s1 = fmaf(xv, d1[k], s1);
                s2 = fmaf(xv, d2[k], s2);
            }
            if (s2 > s1 || (s2 == s1 && I2 < I1)) bi = I2;
        }
        s_idx[tid] = bi;
        s_rep[tid] = (B1 > g_negq[pxbase + tid]) ? 1 : 0;
    }
    __syncthreads();

    // ---------------- epilogue: gather + blend + coalesced writes ------------
    const float* xb = x + (size_t)b * CCH * HWV + hw0;
    float* outb = out + (size_t)b * CCH * HWV + hw0;
    for (int c0 = 0; c0 < CCH; c0 += 64) {
#pragma unroll
        for (int it = 0; it < 8; it++) {
            int lin = it * 256 + tid;
            int p = lin >> 4;
            int cq = (lin & 15) * 4;
            float4 v = *(const float4*)(dict + (size_t)s_idx[p] * CCH + c0 + cq);
            su.rows[p][cq + 0] = v.x;
            su.rows[p][cq + 1] = v.y;
            su.rows[p][cq + 2] = v.z;
            su.rows[p][cq + 3] = v.w;
        }
        __syncthreads();
#pragma unroll
        for (int it = 0; it < 32; it++) {
            int lin = it * 256 + tid;
            int c = c0 + (lin >> 7);
            int p = lin & 127;
            float v = su.rows[p][c - c0];
            if (!s_rep[p]) v = xb[(size_t)c * HWV + p];
            outb[(size_t)c * HWV + p] = v;
        }
        __syncthreads();
    }
}

// ---------------- launch ------------------------------------------------------
extern "C" void kernel_launch(void* const* d_in, const int* in_sizes, int n_in,
                              void* d_out, int out_size) {
    const float* x;
    const float* nd;
    if (n_in >= 2 && in_sizes[0] == ND * CCH && in_sizes[1] != ND * CCH) {
        nd = (const float*)d_in[0];
        x  = (const float*)d_in[1];
    } else {
        x  = (const float*)d_in[0];
        nd = (const float*)d_in[1];
    }
    float* out = (float*)d_out;

    cudaFuncSetAttribute(negdict_mma, cudaFuncAttributeMaxDynamicSharedMemorySize,
                         131072);

    prep_dict<<<ND, 128>>>(nd);
    prep_x<<<NPX / 128, 256>>>(x);
    negdict_mma<<<512, 256, 131072>>>(x, nd, out);
}

// round 6
// speedup vs baseline: 2.0777x; 1.0932x over previous
#include <cuda_runtime.h>
#include <cuda_fp16.h>
#include <math.h>
#include <stdint.h>

#define CCH 512
#define ND  512
#define HWV 4096
#define NPX 65536
#define MT  64
#define KCH 32
#define TOTCH 64          // 4 n-tiles * 16 k-chunks
#define MARGIN 1e-5f

#define SW64(o) ((o) ^ (((o) >> 3) & 0x30))

typedef unsigned int u32;

// ---------------- device scratch ----------------
__device__ __align__(16) __half g_Bhi[ND * CCH];
__device__ __align__(16) __half g_Blo[ND * CCH];
__device__ float g_dnorm[ND * CCH];

// ---------------- PTX helpers ----------------
__device__ __forceinline__ u32 smem_u32(const void* p) {
    u32 a;
    asm("{ .reg .u64 t; cvta.to.shared.u64 t, %1; cvt.u32.u64 %0, t; }" : "=r"(a) : "l"(p));
    return a;
}
#define CP16(dst, src) \
    asm volatile("cp.async.cg.shared.global [%0], [%1], 16;" :: "r"(dst), "l"(src) : "memory")
#define CP_COMMIT() asm volatile("cp.async.commit_group;" ::: "memory")
#define CP_WAIT2()  asm volatile("cp.async.wait_group 2;" ::: "memory")

#define LDSM4(r, addr) \
    asm volatile("ldmatrix.sync.aligned.m8n8.x4.shared.b16 {%0,%1,%2,%3}, [%4];" \
        : "=r"((r)[0]), "=r"((r)[1]), "=r"((r)[2]), "=r"((r)[3]) : "r"(addr))

#define MMA16816(d, a, b0, b1) \
    asm volatile("mma.sync.aligned.m16n8k16.row.col.f32.f16.f16.f32 " \
        "{%0,%1,%2,%3},{%4,%5,%6,%7},{%8,%9},{%0,%1,%2,%3};" \
        : "+f"((d)[0]), "+f"((d)[1]), "+f"((d)[2]), "+f"((d)[3]) \
        : "r"((a)[0]), "r"((a)[1]), "r"((a)[2]), "r"((a)[3]), "r"(b0), "r"(b1))

#define STS128(addr, v) \
    asm volatile("st.shared.v4.b32 [%0], {%1,%2,%3,%4};" \
        :: "r"(addr), "r"((v).x), "r"((v).y), "r"((v).z), "r"((v).w) : "memory")

// ---------------- prep: dict -> dnorm fp32 + fp16 hi/lo [n][k] --------------
__global__ void prep_dict(const float* __restrict__ dict) {
    int n = blockIdx.x;
    const float* row = dict + n * CCH;
    float s = 0.f;
    for (int k = threadIdx.x; k < CCH; k += 128) {
        float v = row[k];
        s = fmaf(v, v, s);
    }
#pragma unroll
    for (int o = 16; o; o >>= 1) s += __shfl_xor_sync(0xffffffffu, s, o);
    __shared__ float red[4];
    if ((threadIdx.x & 31) == 0) red[threadIdx.x >> 5] = s;
    __syncthreads();
    float norm = sqrtf(red[0] + red[1] + red[2] + red[3]);
    for (int k = threadIdx.x; k < CCH; k += 128) {
        float v = row[k] / norm;
        g_dnorm[n * CCH + k] = v;
        __half h = __float2half(v);
        g_Bhi[n * CCH + k] = h;
        g_Blo[n * CCH + k] = __float2half(v - __half2float(h));
    }
}

// ---------------- main: fused convert + persistent-A split-fp16 GEMM --------
__global__ void __launch_bounds__(256, 1)
negdict_mma(const float* __restrict__ x, const float* __restrict__ dict,
            float* __restrict__ out) {
    // dyn smem: Ahi 64KB | Alo 64KB | B ring 4 x 16KB  = 192KB
    extern __shared__ __align__(16) char dsm[];
    __shared__ union {
        struct { float bv1[MT][16]; float bv2[MT][16]; int bi1[MT][16]; int bi2[MT][16]; } red;
        float rows[MT][65];
    } su;
    __shared__ float s_negq[MT];
    __shared__ int s_idx[MT];
    __shared__ int s_rep[MT];

    const int tid = threadIdx.x;
    const int wid = tid >> 5;
    const int lid = tid & 31;
    const int wm = wid >> 2;          // 0..1 : 32 px each
    const int wn = wid & 3;           // 0..3 : 32 n each (per n-tile pass)
    const int pxbase = blockIdx.x * MT;
    const int b = pxbase >> 12;
    const int hw0 = pxbase & 4095;
    const float* xb = x + (size_t)b * CCH * HWV + hw0;

    const u32 sA = smem_u32(dsm);              // hi tiles: 16 x 4KB
    const u32 sAlo = sA + 65536;               // lo tiles
    const u32 sB = sA + 131072;                // ring: buf*16KB (hi 8KB | lo 8KB)

    // ldmatrix lane offsets (within a 64px x 32k tile, 64B rows, SW64)
    u32 offA[2], offB[2];
#pragma unroll
    for (int t = 0; t < 2; t++) {
        int rowA = wm * 32 + t * 16 + (lid & 7) + 8 * ((lid >> 3) & 1);
        offA[t] = SW64((u32)(rowA * 64 + ((lid >> 4) << 4)));
    }
#pragma unroll
    for (int g = 0; g < 2; g++) {
        int rowB = wn * 32 + g * 16 + (lid & 7) + 8 * (lid >> 4);
        offB[g] = SW64((u32)(rowB * 64 + (((lid >> 3) & 1) << 4)));
    }

    float acc[2][4][4];
#pragma unroll
    for (int t = 0; t < 2; t++)
#pragma unroll
        for (int j = 0; j < 4; j++)
#pragma unroll
            for (int q = 0; q < 4; q++) acc[t][j][q] = 0.f;

    float bv1s[4], bv2s[4];
    int bi1s[4], bi2s[4];
#pragma unroll
    for (int s = 0; s < 4; s++) {
        bv1s[s] = -1e30f; bv2s[s] = -1e30f;
        bi1s[s] = 0x7fffffff; bi2s[s] = 0x7fffffff;
    }
    float ssqf[4] = {0.f, 0.f, 0.f, 0.f};   // per (t, row-half) ||x||^2 partials

    // x prefetch mapping: px = tid&63, kh = tid>>6 (8 k each)
    const int px_l = tid & 63;
    const int kh = tid >> 6;
    float xr[8];

    auto ldx = [&](int cc) {
        int k0 = (cc & 15) * KCH + kh * 8;
#pragma unroll
        for (int i = 0; i < 8; i++) xr[i] = xb[(size_t)(k0 + i) * HWV + px_l];
    };
    auto cvtsts = [&](int cc) {
        union { __half2 h2[4]; uint4 v; } hi, lo;
#pragma unroll
        for (int i = 0; i < 4; i++) {
            __half h0 = __float2half(xr[2 * i]);
            __half h1 = __float2half(xr[2 * i + 1]);
            hi.h2[i] = __halves2half2(h0, h1);
            lo.h2[i] = __halves2half2(
                __float2half(xr[2 * i]     - __half2float(h0)),
                __float2half(xr[2 * i + 1] - __half2float(h1)));
        }
        u32 dst = (u32)((cc & 15) * 4096) + SW64((u32)(px_l * 64 + kh * 16));
        STS128(sA + dst, hi.v);
        STS128(sAlo + dst, lo.v);
    };
    auto issueB = [&](int cc) {
        u32 bufb = sB + (cc & 3) * 16384;
        int nt = cc >> 4;
        int kc = (cc & 15) * KCH;
#pragma unroll
        for (int it = 0; it < 2; it++) {
            int u = tid + it * 256;         // 0..511 over [row:128][g:4]
            int r = u >> 2;
            int g = u & 3;
            u32 dsw = SW64((u32)(r * 64 + g * 16));
            size_t boff = (size_t)(nt * 128 + r) * CCH + kc + g * 8;
            CP16(bufb + dsw,        g_Bhi + boff);
            CP16(bufb + 8192 + dsw, g_Blo + boff);
        }
        CP_COMMIT();
    };

    // prologue: build A tile 0, start B pipeline
    ldx(0);
    issueB(0); issueB(1); issueB(2);
    cvtsts(0);

    for (int cc = 0; cc < TOTCH; cc++) {
        CP_WAIT2();
        __syncthreads();
        if (cc + 3 < TOTCH) issueB(cc + 3);
        else CP_COMMIT();
        if (cc + 1 < 16) ldx(cc + 1);

        const u32 abase = sA + (cc & 15) * 4096;
        const u32 albase = sAlo + (cc & 15) * 4096;
        const u32 bbase = sB + (cc & 3) * 16384;

        __half2 cA[2], cB[2];
        cA[0] = cA[1] = cB[0] = cB[1] = __halves2half2(__float2half(0.f), __float2half(0.f));

#pragma unroll
        for (int s = 0; s < 2; s++) {
            u32 kx = (u32)(s << 5);
            u32 Ah[2][4], Al[2][4], Bh[2][4], Bl[2][4];
#pragma unroll
            for (int t = 0; t < 2; t++) {
                LDSM4(Ah[t], abase + (offA[t] ^ kx));
                LDSM4(Al[t], albase + (offA[t] ^ kx));
            }
#pragma unroll
            for (int g = 0; g < 2; g++) {
                LDSM4(Bh[g], bbase + (offB[g] ^ kx));
                LDSM4(Bl[g], bbase + 8192 + (offB[g] ^ kx));
            }
            if (cc < 16 && wn == 0) {       // ||x||^2 from hi fragments (pass 0)
#pragma unroll
                for (int t = 0; t < 2; t++) {
                    __half2 a0 = *(__half2*)&Ah[t][0];
                    __half2 a2 = *(__half2*)&Ah[t][2];
                    __half2 a1 = *(__half2*)&Ah[t][1];
                    __half2 a3 = *(__half2*)&Ah[t][3];
                    cA[t] = __hfma2(a0, a0, cA[t]);
                    cA[t] = __hfma2(a2, a2, cA[t]);
                    cB[t] = __hfma2(a1, a1, cB[t]);
                    cB[t] = __hfma2(a3, a3, cB[t]);
                }
            }
#pragma unroll
            for (int t = 0; t < 2; t++)
#pragma unroll
                for (int j = 0; j < 4; j++)
                    MMA16816(acc[t][j], Ah[t], Bh[j >> 1][(j & 1) * 2], Bh[j >> 1][(j & 1) * 2 + 1]);
#pragma unroll
            for (int t = 0; t < 2; t++)
#pragma unroll
                for (int j = 0; j < 4; j++)
                    MMA16816(acc[t][j], Ah[t], Bl[j >> 1][(j & 1) * 2], Bl[j >> 1][(j & 1) * 2 + 1]);
#pragma unroll
            for (int t = 0; t < 2; t++)
#pragma unroll
                for (int j = 0; j < 4; j++)
                    MMA16816(acc[t][j], Al[t], Bh[j >> 1][(j & 1) * 2], Bh[j >> 1][(j & 1) * 2 + 1]);
        }

        if (cc < 16 && wn == 0) {
#pragma unroll
            for (int t = 0; t < 2; t++) {
                ssqf[2 * t]     += __low2float(cA[t]) + __high2float(cA[t]);
                ssqf[2 * t + 1] += __low2float(cB[t]) + __high2float(cB[t]);
            }
        }
        if (cc + 1 < 16) cvtsts(cc + 1);

        if ((cc & 15) == 15) {              // fold n-tile into per-lane top-2
            int nt = cc >> 4;
            int nbase = nt * 128 + wn * 32;
#pragma unroll
            for (int j = 0; j < 4; j++) {
                int nb = nbase + (j >> 1) * 16 + (j & 1) * 8 + 2 * (lid & 3);
#pragma unroll
                for (int t = 0; t < 2; t++) {
#pragma unroll
                    for (int q = 0; q < 4; q++) {
                        int s = 2 * t + (q >> 1);
                        int n = nb + (q & 1);
                        float v = acc[t][j][q];
                        if (v > bv1s[s]) {
                            bv2s[s] = bv1s[s]; bi2s[s] = bi1s[s];
                            bv1s[s] = v;       bi1s[s] = n;
                        } else if (v > bv2s[s]) {
                            bv2s[s] = v; bi2s[s] = n;
                        }
                        acc[t][j][q] = 0.f;
                    }
                }
            }
        }
    }

    // ---------------- negq + cross-lane reduction ----------------------------
    if (wn == 0) {
#pragma unroll
        for (int s = 0; s < 4; s++) {
            float v = ssqf[s];
            v += __shfl_xor_sync(0xffffffffu, v, 1);
            v += __shfl_xor_sync(0xffffffffu, v, 2);
            ssqf[s] = v;
        }
        if ((lid & 3) == 0) {
#pragma unroll
            for (int t = 0; t < 2; t++) {
                int p = wm * 32 + t * 16 + (lid >> 2);
                s_negq[p]     = -0.25f * sqrtf(ssqf[2 * t]);
                s_negq[p + 8] = -0.25f * sqrtf(ssqf[2 * t + 1]);
            }
        }
    }
#pragma unroll
    for (int t = 0; t < 2; t++)
#pragma unroll
        for (int h = 0; h < 2; h++) {
            int s = 2 * t + h;
            int p = wm * 32 + t * 16 + (lid >> 2) + 8 * h;
            int col = wn * 4 + (lid & 3);
            su.red.bv1[p][col] = bv1s[s];
            su.red.bv2[p][col] = bv2s[s];
            su.red.bi1[p][col] = bi1s[s];
            su.red.bi2[p][col] = bi2s[s];
        }
    __syncthreads();

    if (tid < MT) {
        float B1 = -1e30f, B2 = -1e30f;
        int I1 = 0x7fffffff, I2 = 0x7fffffff;
#pragma unroll
        for (int col = 0; col < 16; col++) {
#pragma unroll
            for (int w = 0; w < 2; w++) {
                float v = w ? su.red.bv2[tid][col] : su.red.bv1[tid][col];
                int   i = w ? su.red.bi2[tid][col] : su.red.bi1[tid][col];
                if (v > B1 || (v == B1 && i < I1)) {
                    B2 = B1; I2 = I1; B1 = v; I1 = i;
                } else if (v > B2 || (v == B2 && i < I2)) {
                    B2 = v; I2 = i;
                }
            }
        }
        int bi = I1;
        if (B1 - B2 < MARGIN) {
            const float* xp = xb + tid;
            const float* d1 = g_dnorm + (size_t)I1 * CCH;
            const float* d2 = g_dnorm + (size_t)I2 * CCH;
            float s1 = 0.f, s2 = 0.f;
            for (int k = 0; k < CCH; k++) {
                float xv = xp[(size_t)k * HWV];
                s1 = fmaf(xv, d1[k], s1);
                s2 = fmaf(xv, d2[k], s2);
            }
            if (s2 > s1 || (s2 == s1 && I2 < I1)) bi = I2;
        }
        s_idx[tid] = bi;
        s_rep[tid] = (B1 > s_negq[tid]) ? 1 : 0;
    }
    __syncthreads();

    // ---------------- epilogue: gather + blend + coalesced writes ------------
    float* outb = out + (size_t)b * CCH * HWV + hw0;
    for (int c0 = 0; c0 < CCH; c0 += 64) {
#pragma unroll
        for (int it = 0; it < 4; it++) {
            int lin = it * 256 + tid;       // over [p:64][cq:16]
            int p = lin >> 4;
            int cq = (lin & 15) * 4;
            float4 v = *(const float4*)(dict + (size_t)s_idx[p] * CCH + c0 + cq);
            su.rows[p][cq + 0] = v.x;
            su.rows[p][cq + 1] = v.y;
            su.rows[p][cq + 2] = v.z;
            su.rows[p][cq + 3] = v.w;
        }
        __syncthreads();
#pragma unroll
        for (int it = 0; it < 16; it++) {
            int lin = it * 256 + tid;       // over [c:64][p:64]
            int c = c0 + (lin >> 6);
            int p = lin & 63;
            float v = su.rows[p][c - c0];
            if (!s_rep[p]) v = xb[(size_t)c * HWV + p];
            outb[(size_t)c * HWV + p] = v;
        }
        __syncthreads();
    }
}

// ---------------- launch ------------------------------------------------------
extern "C" void kernel_launch(void* const* d_in, const int* in_sizes, int n_in,
                              void* d_out, int out_size) {
    const float* x;
    const float* nd;
    if (n_in >= 2 && in_sizes[0] == ND * CCH && in_sizes[1] != ND * CCH) {
        nd = (const float*)d_in[0];
        x  = (const float*)d_in[1];
    } else {
        x  = (const float*)d_in[0];
        nd = (const float*)d_in[1];
    }
    float* out = (float*)d_out;

    cudaFuncSetAttribute(negdict_mma, cudaFuncAttributeMaxDynamicSharedMemorySize,
                         196608);

    prep_dict<<<ND, 128>>>(nd);
    negdict_mma<<<NPX / MT, 256, 196608>>>(x, nd, out);
}